// round 13
// baseline (speedup 1.0000x reference)
#include <cuda_runtime.h>
#include <math.h>
#include <stdint.h>

// Problem dims
#define Lx   512
#define Bx   32
#define DIN  42
#define Hx   800
#define H4   3200
#define H2x  1600
#define ASZ  20

// LSTM persistent kernel config
#define NBLK 148      // <= SM count (148/152): co-residency guaranteed
#define NBD  74       // blocks per direction
#define NU   11       // hidden units per block (74*11 >= 800)
#define NTH  352      // 11 warps: warp = unit, lane = batch

// ---------------- scratch (device globals; no allocation) ----------------
__device__ float g_H1[Lx * Bx * H2x];       // layer-0 output  [t][b][1600]
__device__ float g_H2[Lx * Bx * H2x];       // layer-1 output
__device__ float g_G1f[Lx * Bx * H4];       // layer-1 input gates (fwd)
__device__ float g_G1b[Lx * Bx * H4];       // layer-1 input gates (bwd)
__device__ float g_hstate[2 * 2 * Hx * Bx]; // [dir][phase][n][b] double-buffered h
__device__ float g_ang[Lx * Bx * 3];        // predicted torsions
__device__ unsigned int g_arrive = 0;
__device__ volatile unsigned int g_epoch = 0;

// ---------------- software grid barrier (graph-replay safe) ----------------
__device__ __forceinline__ void grid_barrier()
{
    __threadfence();
    __syncthreads();
    if (threadIdx.x == 0) {
        unsigned int my = g_epoch;
        unsigned int a  = atomicAdd(&g_arrive, 1u);
        if (a == gridDim.x - 1u) {
            atomicExch(&g_arrive, 0u);
            __threadfence();
            g_epoch = my + 1u;           // release
        } else {
            while (g_epoch == my) { }    // spin on volatile
        }
        __threadfence();                 // acquire
    }
    __syncthreads();
}

__device__ __forceinline__ float sigf(float v) { return 1.0f / (1.0f + expf(-v)); }

// ---------------- bidirectional LSTM layer (persistent, 1 barrier/step) ----
template<bool IS_L0>
__global__ void __launch_bounds__(NTH, 1)
lstm_kernel(const float* __restrict__ x,
            const float* __restrict__ Wihf, const float* __restrict__ Wihb,
            const float* __restrict__ bihf, const float* __restrict__ bhhf,
            const float* __restrict__ bihb, const float* __restrict__ bhhb,
            const float* __restrict__ Gf,   const float* __restrict__ Gb,
            const float* __restrict__ Whhf, const float* __restrict__ Whhb,
            float* __restrict__ Hout)
{
    extern __shared__ float smem[];
    float* h_sm = smem;                 // [800][32]  (k-major, conflict-free)
    float* x_sm = smem + Hx * Bx;       // [42][32]   (layer0 only)

    const int tid = threadIdx.x;
    const int dir = (blockIdx.x >= NBD) ? 1 : 0;
    const int bi  = blockIdx.x - dir * NBD;
    const int u   = tid >> 5;           // warp id = unit within block
    const int b   = tid & 31;           // lane = batch
    const int n   = bi * NU + u;        // global hidden unit
    const bool valid = (n < Hx);

    const float* Whh = dir ? Whhb : Whhf;
    const float* Wih = dir ? Wihb : Wihf;
    const float* G   = dir ? Gb   : Gf;

    float bi0 = 0.f, bi1 = 0.f, bi2 = 0.f, bi3 = 0.f;
    if (IS_L0 && valid) {
        const float* bih = dir ? bihb : bihf;
        const float* bhh = dir ? bhhb : bhhf;
        bi0 = bih[n]          + bhh[n];
        bi1 = bih[Hx + n]     + bhh[Hx + n];
        bi2 = bih[2 * Hx + n] + bhh[2 * Hx + n];
        bi3 = bih[3 * Hx + n] + bhh[3 * Hx + n];
    }

    // zero phase-0 h-state for owned units, then make globally visible
    if (valid) g_hstate[(dir * 2 + 0) * (Hx * Bx) + n * Bx + b] = 0.f;
    float creg = 0.f;                   // cell state lives in a register forever
    grid_barrier();

    const float* w0 = valid ? (Whh + (size_t)n * Hx) : Whh;
    const float* w1 = w0 + (size_t)Hx * Hx;
    const float* w2 = w1 + (size_t)Hx * Hx;
    const float* w3 = w2 + (size_t)Hx * Hx;

    for (int s = 0; s < Lx; s++) {
        const int t = dir ? (Lx - 1 - s) : s;

        // stage previous h (whole direction) into SMEM; __ldcg avoids stale L1
        {
            const float4* hs4 = (const float4*)(g_hstate + ((dir << 1) + (s & 1)) * (Hx * Bx));
            float4* hd4 = (float4*)h_sm;
            for (int i = tid; i < (Hx * Bx / 4); i += NTH) hd4[i] = __ldcg(hs4 + i);
        }
        if (IS_L0) {
            const float* xr = x + (size_t)t * Bx * DIN;
            for (int i = tid; i < Bx * DIN; i += NTH) {
                int bb = i / DIN; int kk = i - bb * DIN;
                x_sm[kk * Bx + bb] = xr[i];
            }
        }
        __syncthreads();

        if (valid) {
            float a0 = 0.f, a1 = 0.f, a2 = 0.f, a3 = 0.f;
            #pragma unroll 2
            for (int k = 0; k < Hx; k += 4) {
                const float h0 = h_sm[k * Bx + b];
                const float h1 = h_sm[k * Bx + Bx + b];
                const float h2 = h_sm[k * Bx + 2 * Bx + b];
                const float h3 = h_sm[k * Bx + 3 * Bx + b];
                float4 q;
                q = *(const float4*)(w0 + k); a0 += h0 * q.x + h1 * q.y + h2 * q.z + h3 * q.w;
                q = *(const float4*)(w1 + k); a1 += h0 * q.x + h1 * q.y + h2 * q.z + h3 * q.w;
                q = *(const float4*)(w2 + k); a2 += h0 * q.x + h1 * q.y + h2 * q.z + h3 * q.w;
                q = *(const float4*)(w3 + k); a3 += h0 * q.x + h1 * q.y + h2 * q.z + h3 * q.w;
            }
            if (IS_L0) {
                // fused input projection (K=42, ~5% of recurrent work)
                const float* wi0 = Wih + n * DIN;
                const float* wi1 = wi0 + Hx * DIN;
                const float* wi2 = wi1 + Hx * DIN;
                const float* wi3 = wi2 + Hx * DIN;
                #pragma unroll
                for (int k = 0; k < DIN; k++) {
                    const float xv = x_sm[k * Bx + b];
                    a0 += xv * wi0[k]; a1 += xv * wi1[k];
                    a2 += xv * wi2[k]; a3 += xv * wi3[k];
                }
                a0 += bi0; a1 += bi1; a2 += bi2; a3 += bi3;
            } else {
                const float* gp = G + ((size_t)t * Bx + b) * H4 + n;
                a0 += gp[0]; a1 += gp[Hx]; a2 += gp[2 * Hx]; a3 += gp[3 * Hx];
            }
            const float ig = sigf(a0);
            const float fg = sigf(a1);
            const float gg = tanhf(a2);
            const float og = sigf(a3);
            creg = fg * creg + ig * gg;
            const float h = og * tanhf(creg);
            g_hstate[((dir << 1) + ((s + 1) & 1)) * (Hx * Bx) + n * Bx + b] = h;
            Hout[((size_t)t * Bx + b) * H2x + dir * Hx + n] = h;
        }
        grid_barrier();
    }
}

// ---------------- SGEMM:  C[m][n] = sum_k A[m][k]*B[n][k] + bias1[n]+bias2[n]
// 128x128 tile, BK=16, 8x8 microtile, 256 threads. Needs M,N%128==0, K%16==0.
__global__ void __launch_bounds__(256)
sgemm_tt(const float* __restrict__ A, const float* __restrict__ B,
         const float* __restrict__ bias1, const float* __restrict__ bias2,
         float* __restrict__ C, int M, int N, int K)
{
    __shared__ float As[16][128];
    __shared__ float Bs[16][128];
    const int tid = threadIdx.x;
    const int m0 = blockIdx.y << 7;
    const int n0 = blockIdx.x << 7;
    const int tx = tid & 15, ty = tid >> 4;
    const int lr = tid & 127;
    const int lk = (tid >> 7) << 3;     // 0 or 8

    float acc[8][8];
    #pragma unroll
    for (int i = 0; i < 8; i++)
        #pragma unroll
        for (int j = 0; j < 8; j++) acc[i][j] = 0.f;

    const float* Ap = A + (size_t)(m0 + lr) * K + lk;
    const float* Bp = B + (size_t)(n0 + lr) * K + lk;

    for (int k0 = 0; k0 < K; k0 += 16) {
        float4 av0 = *(const float4*)(Ap + k0);
        float4 av1 = *(const float4*)(Ap + k0 + 4);
        float4 bv0 = *(const float4*)(Bp + k0);
        float4 bv1 = *(const float4*)(Bp + k0 + 4);
        As[lk + 0][lr] = av0.x; As[lk + 1][lr] = av0.y; As[lk + 2][lr] = av0.z; As[lk + 3][lr] = av0.w;
        As[lk + 4][lr] = av1.x; As[lk + 5][lr] = av1.y; As[lk + 6][lr] = av1.z; As[lk + 7][lr] = av1.w;
        Bs[lk + 0][lr] = bv0.x; Bs[lk + 1][lr] = bv0.y; Bs[lk + 2][lr] = bv0.z; Bs[lk + 3][lr] = bv0.w;
        Bs[lk + 4][lr] = bv1.x; Bs[lk + 5][lr] = bv1.y; Bs[lk + 6][lr] = bv1.z; Bs[lk + 7][lr] = bv1.w;
        __syncthreads();
        #pragma unroll
        for (int kk = 0; kk < 16; kk++) {
            float ra[8], rb[8];
            *(float4*)&ra[0] = *(const float4*)&As[kk][ty * 8];
            *(float4*)&ra[4] = *(const float4*)&As[kk][ty * 8 + 4];
            *(float4*)&rb[0] = *(const float4*)&Bs[kk][tx * 8];
            *(float4*)&rb[4] = *(const float4*)&Bs[kk][tx * 8 + 4];
            #pragma unroll
            for (int i = 0; i < 8; i++)
                #pragma unroll
                for (int j = 0; j < 8; j++) acc[i][j] += ra[i] * rb[j];
        }
        __syncthreads();
    }

    float bz[8];
    #pragma unroll
    for (int j = 0; j < 8; j++) {
        int nn = n0 + tx * 8 + j;
        bz[j] = (bias1 ? bias1[nn] : 0.f) + (bias2 ? bias2[nn] : 0.f);
    }
    #pragma unroll
    for (int i = 0; i < 8; i++) {
        float* Crow = C + (size_t)(m0 + ty * 8 + i) * N + n0 + tx * 8;
        float4 o0 = { acc[i][0] + bz[0], acc[i][1] + bz[1], acc[i][2] + bz[2], acc[i][3] + bz[3] };
        float4 o1 = { acc[i][4] + bz[4], acc[i][5] + bz[5], acc[i][6] + bz[6], acc[i][7] + bz[7] };
        *(float4*)(Crow)     = o0;
        *(float4*)(Crow + 4) = o1;
    }
}

// ---------------- head: logits -> softmax -> angle mixture -> atan2 --------
__global__ void __launch_bounds__(128)
head_kernel(const float* __restrict__ H2p, const float* __restrict__ Wlin,
            const float* __restrict__ blin, const float* __restrict__ alpha,
            float* __restrict__ ang)
{
    __shared__ float hs[H2x];
    __shared__ float lg[ASZ];
    const int lb = blockIdx.x;               // t*32 + b
    const int tid = threadIdx.x;
    const int w = tid >> 5, lane = tid & 31;

    const float4* hrow = (const float4*)(H2p + (size_t)lb * H2x);
    for (int i = tid; i < H2x / 4; i += 128) ((float4*)hs)[i] = hrow[i];
    __syncthreads();

    for (int a = w; a < ASZ; a += 4) {
        const float* wr = Wlin + a * H2x;
        float s = 0.f;
        for (int k = lane; k < H2x; k += 32) s += hs[k] * wr[k];
        #pragma unroll
        for (int o = 16; o; o >>= 1) s += __shfl_xor_sync(0xffffffffu, s, o);
        if (lane == 0) lg[a] = s + blin[a];
    }
    __syncthreads();

    if (tid < 32) {
        float v = (lane < ASZ) ? lg[lane] : -1e30f;
        float mx = v;
        #pragma unroll
        for (int o = 16; o; o >>= 1) mx = fmaxf(mx, __shfl_xor_sync(0xffffffffu, mx, o));
        float e = (lane < ASZ) ? expf(v - mx) : 0.f;
        float se = e;
        #pragma unroll
        for (int o = 16; o; o >>= 1) se += __shfl_xor_sync(0xffffffffu, se, o);
        const float p = e / se;
        #pragma unroll
        for (int d = 0; d < 3; d++) {
            float al = (lane < ASZ) ? alpha[lane * 3 + d] : 0.f;
            float ss = p * sinf(al);
            float cc = p * cosf(al);
            #pragma unroll
            for (int o = 16; o; o >>= 1) {
                ss += __shfl_xor_sync(0xffffffffu, ss, o);
                cc += __shfl_xor_sync(0xffffffffu, cc, o);
            }
            if (lane == 0) ang[(size_t)lb * 3 + d] = atan2f(ss, cc);
        }
    }
}

// ---------------- NeRF chain extension (one lane per batch column) ---------
__global__ void __launch_bounds__(32)
nerf_kernel(const float* __restrict__ ang, float* __restrict__ out)
{
    const int b = threadIdx.x;
    const float dl[3]    = { 1.458f, 1.525f, 1.329f };
    const float costh[3] = { (float)cos(3.14159265358979323846 - 2.124),
                             (float)cos(3.14159265358979323846 - 1.941),
                             (float)cos(3.14159265358979323846 - 2.028) };
    const float sinth[3] = { (float)sin(3.14159265358979323846 - 2.124),
                             (float)sin(3.14159265358979323846 - 1.941),
                             (float)sin(3.14159265358979323846 - 2.028) };

    float Ax = 0.f, Ay = 0.f, Az = 0.f;
    float Bxv = 1.458f, Byv = 0.f, Bzv = 0.f;
    float Cx = (float)(1.458 + 1.525 * cos(3.14159265358979323846 - 2.124));
    float Cy = (float)(1.525 * sin(3.14159265358979323846 - 2.124));
    float Cz = 0.f;

    for (int i = 0; i < 3 * Lx; i++) {
        const int l = i / 3, d3 = i - l * 3;
        const float phi = ang[((size_t)l * Bx + b) * 3 + d3];

        float bcx = Cx - Bxv, bcy = Cy - Byv, bcz = Cz - Bzv;
        float nb = sqrtf(bcx * bcx + bcy * bcy + bcz * bcz);
        float inv = 1.f / (nb + 1e-8f);
        bcx *= inv; bcy *= inv; bcz *= inv;

        float abx = Bxv - Ax, aby = Byv - Ay, abz = Bzv - Az;
        float nx = aby * bcz - abz * bcy;
        float ny = abz * bcx - abx * bcz;
        float nz = abx * bcy - aby * bcx;
        float nn = sqrtf(nx * nx + ny * ny + nz * nz);
        float invn = 1.f / (nn + 1e-8f);
        nx *= invn; ny *= invn; nz *= invn;

        float mx = ny * bcz - nz * bcy;
        float my = nz * bcx - nx * bcz;
        float mz = nx * bcy - ny * bcx;

        const float cp = cosf(phi), sp = sinf(phi);
        const float ct = costh[d3], st = sinth[d3], dd = dl[d3];

        float Nx = Cx + dd * (ct * bcx + st * (cp * mx + sp * nx));
        float Ny = Cy + dd * (ct * bcy + st * (cp * my + sp * ny));
        float Nz = Cz + dd * (ct * bcz + st * (cp * mz + sp * nz));

        float* o = out + ((size_t)i * Bx + b) * 3;
        o[0] = Nx; o[1] = Ny; o[2] = Nz;

        Ax = Bxv; Ay = Byv; Az = Bzv;
        Bxv = Cx; Byv = Cy; Bzv = Cz;
        Cx = Nx; Cy = Ny; Cz = Nz;
    }
}

// ---------------- launcher ----------------
extern "C" void kernel_launch(void* const* d_in, const int* in_sizes, int n_in,
                              void* d_out, int out_size)
{
    const float* x     = (const float*)d_in[0];
    const float* Wih0f = (const float*)d_in[1];
    const float* Whh0f = (const float*)d_in[2];
    const float* bih0f = (const float*)d_in[3];
    const float* bhh0f = (const float*)d_in[4];
    const float* Wih0b = (const float*)d_in[5];
    const float* Whh0b = (const float*)d_in[6];
    const float* bih0b = (const float*)d_in[7];
    const float* bhh0b = (const float*)d_in[8];
    const float* Wih1f = (const float*)d_in[9];
    const float* Whh1f = (const float*)d_in[10];
    const float* bih1f = (const float*)d_in[11];
    const float* bhh1f = (const float*)d_in[12];
    const float* Wih1b = (const float*)d_in[13];
    const float* Whh1b = (const float*)d_in[14];
    const float* bih1b = (const float*)d_in[15];
    const float* bhh1b = (const float*)d_in[16];
    const float* W_lin = (const float*)d_in[17];
    const float* b_lin = (const float*)d_in[18];
    const float* alpha = (const float*)d_in[19];
    float* out = (float*)d_out;

    float *pH1, *pH2, *pGf, *pGb, *pAng;
    cudaGetSymbolAddress((void**)&pH1,  g_H1);
    cudaGetSymbolAddress((void**)&pH2,  g_H2);
    cudaGetSymbolAddress((void**)&pGf,  g_G1f);
    cudaGetSymbolAddress((void**)&pGb,  g_G1b);
    cudaGetSymbolAddress((void**)&pAng, g_ang);

    const int smem = (Hx * Bx + Bx * DIN) * (int)sizeof(float);
    cudaFuncSetAttribute(lstm_kernel<true>,  cudaFuncAttributeMaxDynamicSharedMemorySize, smem);
    cudaFuncSetAttribute(lstm_kernel<false>, cudaFuncAttributeMaxDynamicSharedMemorySize, smem);

    // Layer 0 (input projection fused; K=42)
    lstm_kernel<true><<<NBLK, NTH, smem>>>(x, Wih0f, Wih0b, bih0f, bhh0f, bih0b, bhh0b,
                                           nullptr, nullptr, Whh0f, Whh0b, pH1);

    // Layer-1 input gates: two big GEMMs with fused biases
    dim3 gg(H4 / 128, (Lx * Bx) / 128);
    sgemm_tt<<<gg, 256>>>(pH1, Wih1f, bih1f, bhh1f, pGf, Lx * Bx, H4, H2x);
    sgemm_tt<<<gg, 256>>>(pH1, Wih1b, bih1b, bhh1b, pGb, Lx * Bx, H4, H2x);

    // Layer 1 (gates precomputed)
    lstm_kernel<false><<<NBLK, NTH, smem>>>(nullptr, nullptr, nullptr,
                                            nullptr, nullptr, nullptr, nullptr,
                                            pGf, pGb, Whh1f, Whh1b, pH2);

    head_kernel<<<Lx * Bx, 128>>>(pH2, W_lin, b_lin, alpha, pAng);
    nerf_kernel<<<1, 32>>>(pAng, out);
}

// round 14
// speedup vs baseline: 1.0021x; 1.0021x over previous
#include <cuda_runtime.h>
#include <math.h>
#include <stdint.h>

// Problem dims
#define Lx   512
#define Bx   32
#define DIN  42
#define Hx   800
#define H4   3200
#define H2x  1600
#define ASZ  20

// LSTM persistent kernel config
#define NBLK 148      // <= SM count (148/152): co-residency guaranteed
#define NBD  74       // blocks per direction
#define NU   11       // hidden units per block (74*11 >= 800)
#define NTH  352      // 11 warps: warp = unit, lane = batch

// ---------------- scratch (device globals; no allocation) ----------------
__device__ float g_H1[Lx * Bx * H2x];       // layer-0 output  [t][b][1600]
__device__ float g_H2[Lx * Bx * H2x];       // layer-1 output
__device__ float g_G1f[Lx * Bx * H4];       // layer-1 input gates (fwd)
__device__ float g_G1b[Lx * Bx * H4];       // layer-1 input gates (bwd)
__device__ float g_hstate[2 * 2 * Hx * Bx]; // [dir][phase][n][b] double-buffered h
__device__ float g_ang[Lx * Bx * 3];        // predicted torsions
__device__ unsigned int g_arrive = 0;
__device__ volatile unsigned int g_epoch = 0;

// ---------------- software grid barrier (graph-replay safe) ----------------
__device__ __forceinline__ void grid_barrier()
{
    __threadfence();
    __syncthreads();
    if (threadIdx.x == 0) {
        unsigned int my = g_epoch;
        unsigned int a  = atomicAdd(&g_arrive, 1u);
        if (a == gridDim.x - 1u) {
            atomicExch(&g_arrive, 0u);
            __threadfence();
            g_epoch = my + 1u;           // release
        } else {
            while (g_epoch == my) { }    // spin on volatile
        }
        __threadfence();                 // acquire
    }
    __syncthreads();
}

__device__ __forceinline__ float sigf(float v) { return 1.0f / (1.0f + expf(-v)); }

// ---------------- bidirectional LSTM layer (persistent, 1 barrier/step) ----
template<bool IS_L0>
__global__ void __launch_bounds__(NTH, 1)
lstm_kernel(const float* __restrict__ x,
            const float* __restrict__ Wihf, const float* __restrict__ Wihb,
            const float* __restrict__ bihf, const float* __restrict__ bhhf,
            const float* __restrict__ bihb, const float* __restrict__ bhhb,
            const float* __restrict__ Gf,   const float* __restrict__ Gb,
            const float* __restrict__ Whhf, const float* __restrict__ Whhb,
            float* __restrict__ Hout)
{
    extern __shared__ float smem[];
    float* h_sm = smem;                 // [800][32]  (k-major, conflict-free)
    float* x_sm = smem + Hx * Bx;       // [42][32]   (layer0 only)

    const int tid = threadIdx.x;
    const int dir = (blockIdx.x >= NBD) ? 1 : 0;
    const int bi  = blockIdx.x - dir * NBD;
    const int u   = tid >> 5;           // warp id = unit within block
    const int b   = tid & 31;           // lane = batch
    const int n   = bi * NU + u;        // global hidden unit
    const bool valid = (n < Hx);

    const float* Whh = dir ? Whhb : Whhf;
    const float* Wih = dir ? Wihb : Wihf;
    const float* G   = dir ? Gb   : Gf;

    float bi0 = 0.f, bi1 = 0.f, bi2 = 0.f, bi3 = 0.f;
    if (IS_L0 && valid) {
        const float* bih = dir ? bihb : bihf;
        const float* bhh = dir ? bhhb : bhhf;
        bi0 = bih[n]          + bhh[n];
        bi1 = bih[Hx + n]     + bhh[Hx + n];
        bi2 = bih[2 * Hx + n] + bhh[2 * Hx + n];
        bi3 = bih[3 * Hx + n] + bhh[3 * Hx + n];
    }

    // zero phase-0 h-state for owned units, then make globally visible
    if (valid) g_hstate[(dir * 2 + 0) * (Hx * Bx) + n * Bx + b] = 0.f;
    float creg = 0.f;                   // cell state lives in a register forever
    grid_barrier();

    const float* w0 = valid ? (Whh + (size_t)n * Hx) : Whh;
    const float* w1 = w0 + (size_t)Hx * Hx;
    const float* w2 = w1 + (size_t)Hx * Hx;
    const float* w3 = w2 + (size_t)Hx * Hx;

    for (int s = 0; s < Lx; s++) {
        const int t = dir ? (Lx - 1 - s) : s;

        // stage previous h (whole direction) into SMEM; __ldcg avoids stale L1
        {
            const float4* hs4 = (const float4*)(g_hstate + ((dir << 1) + (s & 1)) * (Hx * Bx));
            float4* hd4 = (float4*)h_sm;
            for (int i = tid; i < (Hx * Bx / 4); i += NTH) hd4[i] = __ldcg(hs4 + i);
        }
        if (IS_L0) {
            const float* xr = x + (size_t)t * Bx * DIN;
            for (int i = tid; i < Bx * DIN; i += NTH) {
                int bb = i / DIN; int kk = i - bb * DIN;
                x_sm[kk * Bx + bb] = xr[i];
            }
        }
        __syncthreads();

        if (valid) {
            float a0 = 0.f, a1 = 0.f, a2 = 0.f, a3 = 0.f;
            #pragma unroll 2
            for (int k = 0; k < Hx; k += 4) {
                const float h0 = h_sm[k * Bx + b];
                const float h1 = h_sm[k * Bx + Bx + b];
                const float h2 = h_sm[k * Bx + 2 * Bx + b];
                const float h3 = h_sm[k * Bx + 3 * Bx + b];
                float4 q;
                q = *(const float4*)(w0 + k); a0 += h0 * q.x + h1 * q.y + h2 * q.z + h3 * q.w;
                q = *(const float4*)(w1 + k); a1 += h0 * q.x + h1 * q.y + h2 * q.z + h3 * q.w;
                q = *(const float4*)(w2 + k); a2 += h0 * q.x + h1 * q.y + h2 * q.z + h3 * q.w;
                q = *(const float4*)(w3 + k); a3 += h0 * q.x + h1 * q.y + h2 * q.z + h3 * q.w;
            }
            if (IS_L0) {
                // fused input projection (K=42, ~5% of recurrent work)
                const float* wi0 = Wih + n * DIN;
                const float* wi1 = wi0 + Hx * DIN;
                const float* wi2 = wi1 + Hx * DIN;
                const float* wi3 = wi2 + Hx * DIN;
                #pragma unroll
                for (int k = 0; k < DIN; k++) {
                    const float xv = x_sm[k * Bx + b];
                    a0 += xv * wi0[k]; a1 += xv * wi1[k];
                    a2 += xv * wi2[k]; a3 += xv * wi3[k];
                }
                a0 += bi0; a1 += bi1; a2 += bi2; a3 += bi3;
            } else {
                const float* gp = G + ((size_t)t * Bx + b) * H4 + n;
                a0 += gp[0]; a1 += gp[Hx]; a2 += gp[2 * Hx]; a3 += gp[3 * Hx];
            }
            const float ig = sigf(a0);
            const float fg = sigf(a1);
            const float gg = tanhf(a2);
            const float og = sigf(a3);
            creg = fg * creg + ig * gg;
            const float h = og * tanhf(creg);
            g_hstate[((dir << 1) + ((s + 1) & 1)) * (Hx * Bx) + n * Bx + b] = h;
            Hout[((size_t)t * Bx + b) * H2x + dir * Hx + n] = h;
        }
        grid_barrier();
    }
}

// ---------------- SGEMM:  C[m][n] = sum_k A[m][k]*B[n][k] + bias1[n]+bias2[n]
// 128x128 tile, BK=16, 8x8 microtile, 256 threads. Needs M,N%128==0, K%16==0.
__global__ void __launch_bounds__(256)
sgemm_tt(const float* __restrict__ A, const float* __restrict__ B,
         const float* __restrict__ bias1, const float* __restrict__ bias2,
         float* __restrict__ C, int M, int N, int K)
{
    __shared__ float As[16][128];
    __shared__ float Bs[16][128];
    const int tid = threadIdx.x;
    const int m0 = blockIdx.y << 7;
    const int n0 = blockIdx.x << 7;
    const int tx = tid & 15, ty = tid >> 4;
    const int lr = tid & 127;
    const int lk = (tid >> 7) << 3;     // 0 or 8

    float acc[8][8];
    #pragma unroll
    for (int i = 0; i < 8; i++)
        #pragma unroll
        for (int j = 0; j < 8; j++) acc[i][j] = 0.f;

    const float* Ap = A + (size_t)(m0 + lr) * K + lk;
    const float* Bp = B + (size_t)(n0 + lr) * K + lk;

    for (int k0 = 0; k0 < K; k0 += 16) {
        float4 av0 = *(const float4*)(Ap + k0);
        float4 av1 = *(const float4*)(Ap + k0 + 4);
        float4 bv0 = *(const float4*)(Bp + k0);
        float4 bv1 = *(const float4*)(Bp + k0 + 4);
        As[lk + 0][lr] = av0.x; As[lk + 1][lr] = av0.y; As[lk + 2][lr] = av0.z; As[lk + 3][lr] = av0.w;
        As[lk + 4][lr] = av1.x; As[lk + 5][lr] = av1.y; As[lk + 6][lr] = av1.z; As[lk + 7][lr] = av1.w;
        Bs[lk + 0][lr] = bv0.x; Bs[lk + 1][lr] = bv0.y; Bs[lk + 2][lr] = bv0.z; Bs[lk + 3][lr] = bv0.w;
        Bs[lk + 4][lr] = bv1.x; Bs[lk + 5][lr] = bv1.y; Bs[lk + 6][lr] = bv1.z; Bs[lk + 7][lr] = bv1.w;
        __syncthreads();
        #pragma unroll
        for (int kk = 0; kk < 16; kk++) {
            float ra[8], rb[8];
            *(float4*)&ra[0] = *(const float4*)&As[kk][ty * 8];
            *(float4*)&ra[4] = *(const float4*)&As[kk][ty * 8 + 4];
            *(float4*)&rb[0] = *(const float4*)&Bs[kk][tx * 8];
            *(float4*)&rb[4] = *(const float4*)&Bs[kk][tx * 8 + 4];
            #pragma unroll
            for (int i = 0; i < 8; i++)
                #pragma unroll
                for (int j = 0; j < 8; j++) acc[i][j] += ra[i] * rb[j];
        }
        __syncthreads();
    }

    float bz[8];
    #pragma unroll
    for (int j = 0; j < 8; j++) {
        int nn = n0 + tx * 8 + j;
        bz[j] = (bias1 ? bias1[nn] : 0.f) + (bias2 ? bias2[nn] : 0.f);
    }
    #pragma unroll
    for (int i = 0; i < 8; i++) {
        float* Crow = C + (size_t)(m0 + ty * 8 + i) * N + n0 + tx * 8;
        float4 o0 = { acc[i][0] + bz[0], acc[i][1] + bz[1], acc[i][2] + bz[2], acc[i][3] + bz[3] };
        float4 o1 = { acc[i][4] + bz[4], acc[i][5] + bz[5], acc[i][6] + bz[6], acc[i][7] + bz[7] };
        *(float4*)(Crow)     = o0;
        *(float4*)(Crow + 4) = o1;
    }
}

// ---------------- head: logits -> softmax -> angle mixture -> atan2 --------
__global__ void __launch_bounds__(128)
head_kernel(const float* __restrict__ H2p, const float* __restrict__ Wlin,
            const float* __restrict__ blin, const float* __restrict__ alpha,
            float* __restrict__ ang)
{
    __shared__ float hs[H2x];
    __shared__ float lg[ASZ];
    const int lb = blockIdx.x;               // t*32 + b
    const int tid = threadIdx.x;
    const int w = tid >> 5, lane = tid & 31;

    const float4* hrow = (const float4*)(H2p + (size_t)lb * H2x);
    for (int i = tid; i < H2x / 4; i += 128) ((float4*)hs)[i] = hrow[i];
    __syncthreads();

    for (int a = w; a < ASZ; a += 4) {
        const float* wr = Wlin + a * H2x;
        float s = 0.f;
        for (int k = lane; k < H2x; k += 32) s += hs[k] * wr[k];
        #pragma unroll
        for (int o = 16; o; o >>= 1) s += __shfl_xor_sync(0xffffffffu, s, o);
        if (lane == 0) lg[a] = s + blin[a];
    }
    __syncthreads();

    if (tid < 32) {
        float v = (lane < ASZ) ? lg[lane] : -1e30f;
        float mx = v;
        #pragma unroll
        for (int o = 16; o; o >>= 1) mx = fmaxf(mx, __shfl_xor_sync(0xffffffffu, mx, o));
        float e = (lane < ASZ) ? expf(v - mx) : 0.f;
        float se = e;
        #pragma unroll
        for (int o = 16; o; o >>= 1) se += __shfl_xor_sync(0xffffffffu, se, o);
        const float p = e / se;
        #pragma unroll
        for (int d = 0; d < 3; d++) {
            float al = (lane < ASZ) ? alpha[lane * 3 + d] : 0.f;
            float ss = p * sinf(al);
            float cc = p * cosf(al);
            #pragma unroll
            for (int o = 16; o; o >>= 1) {
                ss += __shfl_xor_sync(0xffffffffu, ss, o);
                cc += __shfl_xor_sync(0xffffffffu, cc, o);
            }
            if (lane == 0) ang[(size_t)lb * 3 + d] = atan2f(ss, cc);
        }
    }
}

// ---------------- NeRF chain extension (one lane per batch column) ---------
__global__ void __launch_bounds__(32)
nerf_kernel(const float* __restrict__ ang, float* __restrict__ out)
{
    const int b = threadIdx.x;
    const float dl[3]    = { 1.458f, 1.525f, 1.329f };
    const float costh[3] = { (float)cos(3.14159265358979323846 - 2.124),
                             (float)cos(3.14159265358979323846 - 1.941),
                             (float)cos(3.14159265358979323846 - 2.028) };
    const float sinth[3] = { (float)sin(3.14159265358979323846 - 2.124),
                             (float)sin(3.14159265358979323846 - 1.941),
                             (float)sin(3.14159265358979323846 - 2.028) };

    float Ax = 0.f, Ay = 0.f, Az = 0.f;
    float Bxv = 1.458f, Byv = 0.f, Bzv = 0.f;
    float Cx = (float)(1.458 + 1.525 * cos(3.14159265358979323846 - 2.124));
    float Cy = (float)(1.525 * sin(3.14159265358979323846 - 2.124));
    float Cz = 0.f;

    for (int i = 0; i < 3 * Lx; i++) {
        const int l = i / 3, d3 = i - l * 3;
        const float phi = ang[((size_t)l * Bx + b) * 3 + d3];

        float bcx = Cx - Bxv, bcy = Cy - Byv, bcz = Cz - Bzv;
        float nb = sqrtf(bcx * bcx + bcy * bcy + bcz * bcz);
        float inv = 1.f / (nb + 1e-8f);
        bcx *= inv; bcy *= inv; bcz *= inv;

        float abx = Bxv - Ax, aby = Byv - Ay, abz = Bzv - Az;
        float nx = aby * bcz - abz * bcy;
        float ny = abz * bcx - abx * bcz;
        float nz = abx * bcy - aby * bcx;
        float nn = sqrtf(nx * nx + ny * ny + nz * nz);
        float invn = 1.f / (nn + 1e-8f);
        nx *= invn; ny *= invn; nz *= invn;

        float mx = ny * bcz - nz * bcy;
        float my = nz * bcx - nx * bcz;
        float mz = nx * bcy - ny * bcx;

        const float cp = cosf(phi), sp = sinf(phi);
        const float ct = costh[d3], st = sinth[d3], dd = dl[d3];

        float Nx = Cx + dd * (ct * bcx + st * (cp * mx + sp * nx));
        float Ny = Cy + dd * (ct * bcy + st * (cp * my + sp * ny));
        float Nz = Cz + dd * (ct * bcz + st * (cp * mz + sp * nz));

        float* o = out + ((size_t)i * Bx + b) * 3;
        o[0] = Nx; o[1] = Ny; o[2] = Nz;

        Ax = Bxv; Ay = Byv; Az = Bzv;
        Bxv = Cx; Byv = Cy; Bzv = Cz;
        Cx = Nx; Cy = Ny; Cz = Nz;
    }
}

// ---------------- launcher ----------------
extern "C" void kernel_launch(void* const* d_in, const int* in_sizes, int n_in,
                              void* d_out, int out_size)
{
    const float* x     = (const float*)d_in[0];
    const float* Wih0f = (const float*)d_in[1];
    const float* Whh0f = (const float*)d_in[2];
    const float* bih0f = (const float*)d_in[3];
    const float* bhh0f = (const float*)d_in[4];
    const float* Wih0b = (const float*)d_in[5];
    const float* Whh0b = (const float*)d_in[6];
    const float* bih0b = (const float*)d_in[7];
    const float* bhh0b = (const float*)d_in[8];
    const float* Wih1f = (const float*)d_in[9];
    const float* Whh1f = (const float*)d_in[10];
    const float* bih1f = (const float*)d_in[11];
    const float* bhh1f = (const float*)d_in[12];
    const float* Wih1b = (const float*)d_in[13];
    const float* Whh1b = (const float*)d_in[14];
    const float* bih1b = (const float*)d_in[15];
    const float* bhh1b = (const float*)d_in[16];
    const float* W_lin = (const float*)d_in[17];
    const float* b_lin = (const float*)d_in[18];
    const float* alpha = (const float*)d_in[19];
    float* out = (float*)d_out;

    float *pH1, *pH2, *pGf, *pGb, *pAng;
    cudaGetSymbolAddress((void**)&pH1,  g_H1);
    cudaGetSymbolAddress((void**)&pH2,  g_H2);
    cudaGetSymbolAddress((void**)&pGf,  g_G1f);
    cudaGetSymbolAddress((void**)&pGb,  g_G1b);
    cudaGetSymbolAddress((void**)&pAng, g_ang);

    const int smem = (Hx * Bx + Bx * DIN) * (int)sizeof(float);
    cudaFuncSetAttribute(lstm_kernel<true>,  cudaFuncAttributeMaxDynamicSharedMemorySize, smem);
    cudaFuncSetAttribute(lstm_kernel<false>, cudaFuncAttributeMaxDynamicSharedMemorySize, smem);

    // Layer 0 (input projection fused; K=42)
    lstm_kernel<true><<<NBLK, NTH, smem>>>(x, Wih0f, Wih0b, bih0f, bhh0f, bih0b, bhh0b,
                                           nullptr, nullptr, Whh0f, Whh0b, pH1);

    // Layer-1 input gates: two big GEMMs with fused biases
    dim3 gg(H4 / 128, (Lx * Bx) / 128);
    sgemm_tt<<<gg, 256>>>(pH1, Wih1f, bih1f, bhh1f, pGf, Lx * Bx, H4, H2x);
    sgemm_tt<<<gg, 256>>>(pH1, Wih1b, bih1b, bhh1b, pGb, Lx * Bx, H4, H2x);

    // Layer 1 (gates precomputed)
    lstm_kernel<false><<<NBLK, NTH, smem>>>(nullptr, nullptr, nullptr,
                                            nullptr, nullptr, nullptr, nullptr,
                                            pGf, pGb, Whh1f, Whh1b, pH2);

    head_kernel<<<Lx * Bx, 128>>>(pH2, W_lin, b_lin, alpha, pAng);
    nerf_kernel<<<1, 32>>>(pAng, out);
}

// round 15
// speedup vs baseline: 1.0099x; 1.0078x over previous
#include <cuda_runtime.h>
#include <math.h>
#include <stdint.h>

// Problem dims
#define Lx   512
#define Bx   32
#define DIN  42
#define Hx   800
#define H4   3200
#define H2x  1600
#define ASZ  20

// LSTM persistent kernel config
#define NBLK 148      // <= SM count (148/152): co-residency guaranteed
#define NBD  74       // blocks per direction
#define NU   11       // hidden units per block (74*11 >= 800)
#define NTH  352      // 11 warps: warp = unit, lane = batch

// ---------------- scratch (device globals; no allocation) ----------------
__device__ float g_H1[Lx * Bx * H2x];       // layer-0 output  [t][b][1600]
__device__ float g_H2[Lx * Bx * H2x];       // layer-1 output
__device__ float g_G1f[Lx * Bx * H4];       // layer-1 input gates (fwd)
__device__ float g_G1b[Lx * Bx * H4];       // layer-1 input gates (bwd)
__device__ float g_hstate[2 * 2 * Hx * Bx]; // [dir][phase][n][b] double-buffered h
__device__ float g_ang[Lx * Bx * 3];        // predicted torsions
__device__ unsigned int g_arrive = 0;
__device__ volatile unsigned int g_epoch = 0;

// ---------------- software grid barrier (graph-replay safe) ----------------
__device__ __forceinline__ void grid_barrier()
{
    __threadfence();
    __syncthreads();
    if (threadIdx.x == 0) {
        unsigned int my = g_epoch;
        unsigned int a  = atomicAdd(&g_arrive, 1u);
        if (a == gridDim.x - 1u) {
            atomicExch(&g_arrive, 0u);
            __threadfence();
            g_epoch = my + 1u;           // release
        } else {
            while (g_epoch == my) { }    // spin on volatile
        }
        __threadfence();                 // acquire
    }
    __syncthreads();
}

__device__ __forceinline__ float sigf(float v) { return 1.0f / (1.0f + expf(-v)); }

// ---------------- bidirectional LSTM layer (persistent, 1 barrier/step) ----
template<bool IS_L0>
__global__ void __launch_bounds__(NTH, 1)
lstm_kernel(const float* __restrict__ x,
            const float* __restrict__ Wihf, const float* __restrict__ Wihb,
            const float* __restrict__ bihf, const float* __restrict__ bhhf,
            const float* __restrict__ bihb, const float* __restrict__ bhhb,
            const float* __restrict__ Gf,   const float* __restrict__ Gb,
            const float* __restrict__ Whhf, const float* __restrict__ Whhb,
            float* __restrict__ Hout)
{
    extern __shared__ float smem[];
    float* h_sm = smem;                 // [800][32]  (k-major, conflict-free)
    float* x_sm = smem + Hx * Bx;       // [42][32]   (layer0 only)

    const int tid = threadIdx.x;
    const int dir = (blockIdx.x >= NBD) ? 1 : 0;
    const int bi  = blockIdx.x - dir * NBD;
    const int u   = tid >> 5;           // warp id = unit within block
    const int b   = tid & 31;           // lane = batch
    const int n   = bi * NU + u;        // global hidden unit
    const bool valid = (n < Hx);

    const float* Whh = dir ? Whhb : Whhf;
    const float* Wih = dir ? Wihb : Wihf;
    const float* G   = dir ? Gb   : Gf;

    float bi0 = 0.f, bi1 = 0.f, bi2 = 0.f, bi3 = 0.f;
    if (IS_L0 && valid) {
        const float* bih = dir ? bihb : bihf;
        const float* bhh = dir ? bhhb : bhhf;
        bi0 = bih[n]          + bhh[n];
        bi1 = bih[Hx + n]     + bhh[Hx + n];
        bi2 = bih[2 * Hx + n] + bhh[2 * Hx + n];
        bi3 = bih[3 * Hx + n] + bhh[3 * Hx + n];
    }

    // zero phase-0 h-state for owned units, then make globally visible
    if (valid) g_hstate[(dir * 2 + 0) * (Hx * Bx) + n * Bx + b] = 0.f;
    float creg = 0.f;                   // cell state lives in a register forever
    grid_barrier();

    const float* w0 = valid ? (Whh + (size_t)n * Hx) : Whh;
    const float* w1 = w0 + (size_t)Hx * Hx;
    const float* w2 = w1 + (size_t)Hx * Hx;
    const float* w3 = w2 + (size_t)Hx * Hx;

    for (int s = 0; s < Lx; s++) {
        const int t = dir ? (Lx - 1 - s) : s;

        // stage previous h (whole direction) into SMEM; __ldcg avoids stale L1
        {
            const float4* hs4 = (const float4*)(g_hstate + ((dir << 1) + (s & 1)) * (Hx * Bx));
            float4* hd4 = (float4*)h_sm;
            for (int i = tid; i < (Hx * Bx / 4); i += NTH) hd4[i] = __ldcg(hs4 + i);
        }
        if (IS_L0) {
            const float* xr = x + (size_t)t * Bx * DIN;
            for (int i = tid; i < Bx * DIN; i += NTH) {
                int bb = i / DIN; int kk = i - bb * DIN;
                x_sm[kk * Bx + bb] = xr[i];
            }
        }
        __syncthreads();

        if (valid) {
            float a0 = 0.f, a1 = 0.f, a2 = 0.f, a3 = 0.f;
            #pragma unroll 2
            for (int k = 0; k < Hx; k += 4) {
                const float h0 = h_sm[k * Bx + b];
                const float h1 = h_sm[k * Bx + Bx + b];
                const float h2 = h_sm[k * Bx + 2 * Bx + b];
                const float h3 = h_sm[k * Bx + 3 * Bx + b];
                float4 q;
                q = *(const float4*)(w0 + k); a0 += h0 * q.x + h1 * q.y + h2 * q.z + h3 * q.w;
                q = *(const float4*)(w1 + k); a1 += h0 * q.x + h1 * q.y + h2 * q.z + h3 * q.w;
                q = *(const float4*)(w2 + k); a2 += h0 * q.x + h1 * q.y + h2 * q.z + h3 * q.w;
                q = *(const float4*)(w3 + k); a3 += h0 * q.x + h1 * q.y + h2 * q.z + h3 * q.w;
            }
            if (IS_L0) {
                // fused input projection (K=42, ~5% of recurrent work)
                const float* wi0 = Wih + n * DIN;
                const float* wi1 = wi0 + Hx * DIN;
                const float* wi2 = wi1 + Hx * DIN;
                const float* wi3 = wi2 + Hx * DIN;
                #pragma unroll
                for (int k = 0; k < DIN; k++) {
                    const float xv = x_sm[k * Bx + b];
                    a0 += xv * wi0[k]; a1 += xv * wi1[k];
                    a2 += xv * wi2[k]; a3 += xv * wi3[k];
                }
                a0 += bi0; a1 += bi1; a2 += bi2; a3 += bi3;
            } else {
                const float* gp = G + ((size_t)t * Bx + b) * H4 + n;
                a0 += gp[0]; a1 += gp[Hx]; a2 += gp[2 * Hx]; a3 += gp[3 * Hx];
            }
            const float ig = sigf(a0);
            const float fg = sigf(a1);
            const float gg = tanhf(a2);
            const float og = sigf(a3);
            creg = fg * creg + ig * gg;
            const float h = og * tanhf(creg);
            g_hstate[((dir << 1) + ((s + 1) & 1)) * (Hx * Bx) + n * Bx + b] = h;
            Hout[((size_t)t * Bx + b) * H2x + dir * Hx + n] = h;
        }
        grid_barrier();
    }
}

// ---------------- SGEMM:  C[m][n] = sum_k A[m][k]*B[n][k] + bias1[n]+bias2[n]
// 128x128 tile, BK=16, 8x8 microtile, 256 threads, DOUBLE-BUFFERED smem with
// global->register prefetch. Needs M,N%128==0, K%16==0.
__global__ void __launch_bounds__(256, 2)
sgemm_tt(const float* __restrict__ A, const float* __restrict__ B,
         const float* __restrict__ bias1, const float* __restrict__ bias2,
         float* __restrict__ C, int M, int N, int K)
{
    __shared__ float As[2][16][128];
    __shared__ float Bs[2][16][128];
    const int tid = threadIdx.x;
    const int m0 = blockIdx.y << 7;
    const int n0 = blockIdx.x << 7;
    const int tx = tid & 15, ty = tid >> 4;
    const int lr = tid & 127;
    const int lk = (tid >> 7) << 3;     // 0 or 8

    float acc[8][8];
    #pragma unroll
    for (int i = 0; i < 8; i++)
        #pragma unroll
        for (int j = 0; j < 8; j++) acc[i][j] = 0.f;

    const float* Ap = A + (size_t)(m0 + lr) * K + lk;
    const float* Bp = B + (size_t)(n0 + lr) * K + lk;

    // ---- preload tile 0 into smem[0]
    {
        float4 a0 = *(const float4*)(Ap);
        float4 a1 = *(const float4*)(Ap + 4);
        float4 b0 = *(const float4*)(Bp);
        float4 b1 = *(const float4*)(Bp + 4);
        As[0][lk + 0][lr] = a0.x; As[0][lk + 1][lr] = a0.y; As[0][lk + 2][lr] = a0.z; As[0][lk + 3][lr] = a0.w;
        As[0][lk + 4][lr] = a1.x; As[0][lk + 5][lr] = a1.y; As[0][lk + 6][lr] = a1.z; As[0][lk + 7][lr] = a1.w;
        Bs[0][lk + 0][lr] = b0.x; Bs[0][lk + 1][lr] = b0.y; Bs[0][lk + 2][lr] = b0.z; Bs[0][lk + 3][lr] = b0.w;
        Bs[0][lk + 4][lr] = b1.x; Bs[0][lk + 5][lr] = b1.y; Bs[0][lk + 6][lr] = b1.z; Bs[0][lk + 7][lr] = b1.w;
    }
    __syncthreads();

    const int ktiles = K >> 4;
    int buf = 0;

    for (int kt = 0; kt < ktiles; kt++) {
        // ---- issue global prefetch of next tile EARLY (consumed after compute)
        float4 na0, na1, nb0, nb1;
        const bool has_next = (kt + 1 < ktiles);
        if (has_next) {
            const float* Ap2 = Ap + ((kt + 1) << 4);
            const float* Bp2 = Bp + ((kt + 1) << 4);
            na0 = *(const float4*)(Ap2);
            na1 = *(const float4*)(Ap2 + 4);
            nb0 = *(const float4*)(Bp2);
            nb1 = *(const float4*)(Bp2 + 4);
        }

        // ---- compute on current buffer
        #pragma unroll
        for (int kk = 0; kk < 16; kk++) {
            float ra[8], rb[8];
            *(float4*)&ra[0] = *(const float4*)&As[buf][kk][ty * 8];
            *(float4*)&ra[4] = *(const float4*)&As[buf][kk][ty * 8 + 4];
            *(float4*)&rb[0] = *(const float4*)&Bs[buf][kk][tx * 8];
            *(float4*)&rb[4] = *(const float4*)&Bs[buf][kk][tx * 8 + 4];
            #pragma unroll
            for (int i = 0; i < 8; i++)
                #pragma unroll
                for (int j = 0; j < 8; j++) acc[i][j] += ra[i] * rb[j];
        }

        // ---- store prefetched tile into the other buffer, flip
        if (has_next) {
            const int nb = buf ^ 1;
            As[nb][lk + 0][lr] = na0.x; As[nb][lk + 1][lr] = na0.y; As[nb][lk + 2][lr] = na0.z; As[nb][lk + 3][lr] = na0.w;
            As[nb][lk + 4][lr] = na1.x; As[nb][lk + 5][lr] = na1.y; As[nb][lk + 6][lr] = na1.z; As[nb][lk + 7][lr] = na1.w;
            Bs[nb][lk + 0][lr] = nb0.x; Bs[nb][lk + 1][lr] = nb0.y; Bs[nb][lk + 2][lr] = nb0.z; Bs[nb][lk + 3][lr] = nb0.w;
            Bs[nb][lk + 4][lr] = nb1.x; Bs[nb][lk + 5][lr] = nb1.y; Bs[nb][lk + 6][lr] = nb1.z; Bs[nb][lk + 7][lr] = nb1.w;
            __syncthreads();
            buf = nb;
        }
    }

    float bz[8];
    #pragma unroll
    for (int j = 0; j < 8; j++) {
        int nn = n0 + tx * 8 + j;
        bz[j] = (bias1 ? bias1[nn] : 0.f) + (bias2 ? bias2[nn] : 0.f);
    }
    #pragma unroll
    for (int i = 0; i < 8; i++) {
        float* Crow = C + (size_t)(m0 + ty * 8 + i) * N + n0 + tx * 8;
        float4 o0 = { acc[i][0] + bz[0], acc[i][1] + bz[1], acc[i][2] + bz[2], acc[i][3] + bz[3] };
        float4 o1 = { acc[i][4] + bz[4], acc[i][5] + bz[5], acc[i][6] + bz[6], acc[i][7] + bz[7] };
        *(float4*)(Crow)     = o0;
        *(float4*)(Crow + 4) = o1;
    }
}

// ---------------- head: logits -> softmax -> angle mixture -> atan2 --------
__global__ void __launch_bounds__(128)
head_kernel(const float* __restrict__ H2p, const float* __restrict__ Wlin,
            const float* __restrict__ blin, const float* __restrict__ alpha,
            float* __restrict__ ang)
{
    __shared__ float hs[H2x];
    __shared__ float lg[ASZ];
    const int lb = blockIdx.x;               // t*32 + b
    const int tid = threadIdx.x;
    const int w = tid >> 5, lane = tid & 31;

    const float4* hrow = (const float4*)(H2p + (size_t)lb * H2x);
    for (int i = tid; i < H2x / 4; i += 128) ((float4*)hs)[i] = hrow[i];
    __syncthreads();

    for (int a = w; a < ASZ; a += 4) {
        const float* wr = Wlin + a * H2x;
        float s = 0.f;
        for (int k = lane; k < H2x; k += 32) s += hs[k] * wr[k];
        #pragma unroll
        for (int o = 16; o; o >>= 1) s += __shfl_xor_sync(0xffffffffu, s, o);
        if (lane == 0) lg[a] = s + blin[a];
    }
    __syncthreads();

    if (tid < 32) {
        float v = (lane < ASZ) ? lg[lane] : -1e30f;
        float mx = v;
        #pragma unroll
        for (int o = 16; o; o >>= 1) mx = fmaxf(mx, __shfl_xor_sync(0xffffffffu, mx, o));
        float e = (lane < ASZ) ? expf(v - mx) : 0.f;
        float se = e;
        #pragma unroll
        for (int o = 16; o; o >>= 1) se += __shfl_xor_sync(0xffffffffu, se, o);
        const float p = e / se;
        #pragma unroll
        for (int d = 0; d < 3; d++) {
            float al = (lane < ASZ) ? alpha[lane * 3 + d] : 0.f;
            float ss = p * sinf(al);
            float cc = p * cosf(al);
            #pragma unroll
            for (int o = 16; o; o >>= 1) {
                ss += __shfl_xor_sync(0xffffffffu, ss, o);
                cc += __shfl_xor_sync(0xffffffffu, cc, o);
            }
            if (lane == 0) ang[(size_t)lb * 3 + d] = atan2f(ss, cc);
        }
    }
}

// ---------------- NeRF chain extension (one lane per batch column) ---------
__global__ void __launch_bounds__(32)
nerf_kernel(const float* __restrict__ ang, float* __restrict__ out)
{
    const int b = threadIdx.x;
    const float dl[3]    = { 1.458f, 1.525f, 1.329f };
    const float costh[3] = { (float)cos(3.14159265358979323846 - 2.124),
                             (float)cos(3.14159265358979323846 - 1.941),
                             (float)cos(3.14159265358979323846 - 2.028) };
    const float sinth[3] = { (float)sin(3.14159265358979323846 - 2.124),
                             (float)sin(3.14159265358979323846 - 1.941),
                             (float)sin(3.14159265358979323846 - 2.028) };

    float Ax = 0.f, Ay = 0.f, Az = 0.f;
    float Bxv = 1.458f, Byv = 0.f, Bzv = 0.f;
    float Cx = (float)(1.458 + 1.525 * cos(3.14159265358979323846 - 2.124));
    float Cy = (float)(1.525 * sin(3.14159265358979323846 - 2.124));
    float Cz = 0.f;

    for (int i = 0; i < 3 * Lx; i++) {
        const int l = i / 3, d3 = i - l * 3;
        const float phi = ang[((size_t)l * Bx + b) * 3 + d3];

        float bcx = Cx - Bxv, bcy = Cy - Byv, bcz = Cz - Bzv;
        float nb = sqrtf(bcx * bcx + bcy * bcy + bcz * bcz);
        float inv = 1.f / (nb + 1e-8f);
        bcx *= inv; bcy *= inv; bcz *= inv;

        float abx = Bxv - Ax, aby = Byv - Ay, abz = Bzv - Az;
        float nx = aby * bcz - abz * bcy;
        float ny = abz * bcx - abx * bcz;
        float nz = abx * bcy - aby * bcx;
        float nn = sqrtf(nx * nx + ny * ny + nz * nz);
        float invn = 1.f / (nn + 1e-8f);
        nx *= invn; ny *= invn; nz *= invn;

        float mx = ny * bcz - nz * bcy;
        float my = nz * bcx - nx * bcz;
        float mz = nx * bcy - ny * bcx;

        const float cp = cosf(phi), sp = sinf(phi);
        const float ct = costh[d3], st = sinth[d3], dd = dl[d3];

        float Nx = Cx + dd * (ct * bcx + st * (cp * mx + sp * nx));
        float Ny = Cy + dd * (ct * bcy + st * (cp * my + sp * ny));
        float Nz = Cz + dd * (ct * bcz + st * (cp * mz + sp * nz));

        float* o = out + ((size_t)i * Bx + b) * 3;
        o[0] = Nx; o[1] = Ny; o[2] = Nz;

        Ax = Bxv; Ay = Byv; Az = Bzv;
        Bxv = Cx; Byv = Cy; Bzv = Cz;
        Cx = Nx; Cy = Ny; Cz = Nz;
    }
}

// ---------------- launcher ----------------
extern "C" void kernel_launch(void* const* d_in, const int* in_sizes, int n_in,
                              void* d_out, int out_size)
{
    const float* x     = (const float*)d_in[0];
    const float* Wih0f = (const float*)d_in[1];
    const float* Whh0f = (const float*)d_in[2];
    const float* bih0f = (const float*)d_in[3];
    const float* bhh0f = (const float*)d_in[4];
    const float* Wih0b = (const float*)d_in[5];
    const float* Whh0b = (const float*)d_in[6];
    const float* bih0b = (const float*)d_in[7];
    const float* bhh0b = (const float*)d_in[8];
    const float* Wih1f = (const float*)d_in[9];
    const float* Whh1f = (const float*)d_in[10];
    const float* bih1f = (const float*)d_in[11];
    const float* bhh1f = (const float*)d_in[12];
    const float* Wih1b = (const float*)d_in[13];
    const float* Whh1b = (const float*)d_in[14];
    const float* bih1b = (const float*)d_in[15];
    const float* bhh1b = (const float*)d_in[16];
    const float* W_lin = (const float*)d_in[17];
    const float* b_lin = (const float*)d_in[18];
    const float* alpha = (const float*)d_in[19];
    float* out = (float*)d_out;

    float *pH1, *pH2, *pGf, *pGb, *pAng;
    cudaGetSymbolAddress((void**)&pH1,  g_H1);
    cudaGetSymbolAddress((void**)&pH2,  g_H2);
    cudaGetSymbolAddress((void**)&pGf,  g_G1f);
    cudaGetSymbolAddress((void**)&pGb,  g_G1b);
    cudaGetSymbolAddress((void**)&pAng, g_ang);

    const int smem = (Hx * Bx + Bx * DIN) * (int)sizeof(float);
    cudaFuncSetAttribute(lstm_kernel<true>,  cudaFuncAttributeMaxDynamicSharedMemorySize, smem);
    cudaFuncSetAttribute(lstm_kernel<false>, cudaFuncAttributeMaxDynamicSharedMemorySize, smem);

    // Layer 0 (input projection fused; K=42)
    lstm_kernel<true><<<NBLK, NTH, smem>>>(x, Wih0f, Wih0b, bih0f, bhh0f, bih0b, bhh0b,
                                           nullptr, nullptr, Whh0f, Whh0b, pH1);

    // Layer-1 input gates: two big GEMMs with fused biases
    dim3 gg(H4 / 128, (Lx * Bx) / 128);
    sgemm_tt<<<gg, 256>>>(pH1, Wih1f, bih1f, bhh1f, pGf, Lx * Bx, H4, H2x);
    sgemm_tt<<<gg, 256>>>(pH1, Wih1b, bih1b, bhh1b, pGb, Lx * Bx, H4, H2x);

    // Layer 1 (gates precomputed)
    lstm_kernel<false><<<NBLK, NTH, smem>>>(nullptr, nullptr, nullptr,
                                            nullptr, nullptr, nullptr, nullptr,
                                            pGf, pGb, Whh1f, Whh1b, pH2);

    head_kernel<<<Lx * Bx, 128>>>(pH2, W_lin, b_lin, alpha, pAng);
    nerf_kernel<<<1, 32>>>(pAng, out);
}

// round 16
// speedup vs baseline: 1.0126x; 1.0027x over previous
#include <cuda_runtime.h>
#include <math.h>
#include <stdint.h>

// Problem dims
#define Lx   512
#define Bx   32
#define DIN  42
#define Hx   800
#define H4   3200
#define H2x  1600
#define ASZ  20

// LSTM persistent kernel config
#define NBLK 148      // <= SM count (148/152): co-residency guaranteed
#define NBD  74       // blocks per direction
#define NU   11       // hidden units per block (74*11 >= 800)
#define NTH  352      // 11 warps: warp = unit, lane = batch

// ---------------- scratch (device globals; no allocation) ----------------
__device__ float g_H1[Lx * Bx * H2x];       // layer-0 output  [t][b][1600]
__device__ float g_H2[Lx * Bx * H2x];       // layer-1 output
__device__ float g_G1f[Lx * Bx * H4];       // layer-1 input gates (fwd)
__device__ float g_G1b[Lx * Bx * H4];       // layer-1 input gates (bwd)
__device__ float g_hstate[2 * 2 * Hx * Bx]; // [dir][phase][n][b] double-buffered h
__device__ float g_ang[Lx * Bx * 3];        // predicted torsions
__device__ unsigned int g_arrive = 0;
__device__ volatile unsigned int g_epoch = 0;

// ---------------- software grid barrier (graph-replay safe) ----------------
__device__ __forceinline__ void grid_barrier()
{
    __threadfence();
    __syncthreads();
    if (threadIdx.x == 0) {
        unsigned int my = g_epoch;
        unsigned int a  = atomicAdd(&g_arrive, 1u);
        if (a == gridDim.x - 1u) {
            atomicExch(&g_arrive, 0u);
            __threadfence();
            g_epoch = my + 1u;           // release
        } else {
            while (g_epoch == my) { }    // spin on volatile
        }
        __threadfence();                 // acquire
    }
    __syncthreads();
}

__device__ __forceinline__ float sigf(float v) { return 1.0f / (1.0f + expf(-v)); }

// ---------------- bidirectional LSTM layer (persistent, 1 barrier/step) ----
template<bool IS_L0>
__global__ void __launch_bounds__(NTH, 1)
lstm_kernel(const float* __restrict__ x,
            const float* __restrict__ Wihf, const float* __restrict__ Wihb,
            const float* __restrict__ bihf, const float* __restrict__ bhhf,
            const float* __restrict__ bihb, const float* __restrict__ bhhb,
            const float* __restrict__ Gf,   const float* __restrict__ Gb,
            const float* __restrict__ Whhf, const float* __restrict__ Whhb,
            float* __restrict__ Hout)
{
    extern __shared__ float smem[];
    float* h_sm = smem;                 // [800][32]  (k-major, conflict-free)
    float* x_sm = smem + Hx * Bx;       // [42][32]   (layer0 only)

    const int tid = threadIdx.x;
    const int dir = (blockIdx.x >= NBD) ? 1 : 0;
    const int bi  = blockIdx.x - dir * NBD;
    const int u   = tid >> 5;           // warp id = unit within block
    const int b   = tid & 31;           // lane = batch
    const int n   = bi * NU + u;        // global hidden unit
    const bool valid = (n < Hx);

    const float* Whh = dir ? Whhb : Whhf;
    const float* Wih = dir ? Wihb : Wihf;
    const float* G   = dir ? Gb   : Gf;

    float bi0 = 0.f, bi1 = 0.f, bi2 = 0.f, bi3 = 0.f;
    if (IS_L0 && valid) {
        const float* bih = dir ? bihb : bihf;
        const float* bhh = dir ? bhhb : bhhf;
        bi0 = bih[n]          + bhh[n];
        bi1 = bih[Hx + n]     + bhh[Hx + n];
        bi2 = bih[2 * Hx + n] + bhh[2 * Hx + n];
        bi3 = bih[3 * Hx + n] + bhh[3 * Hx + n];
    }

    // zero phase-0 h-state for owned units, then make globally visible
    if (valid) g_hstate[(dir * 2 + 0) * (Hx * Bx) + n * Bx + b] = 0.f;
    float creg = 0.f;                   // cell state lives in a register forever
    grid_barrier();

    const float* w0 = valid ? (Whh + (size_t)n * Hx) : Whh;
    const float* w1 = w0 + (size_t)Hx * Hx;
    const float* w2 = w1 + (size_t)Hx * Hx;
    const float* w3 = w2 + (size_t)Hx * Hx;

    for (int s = 0; s < Lx; s++) {
        const int t = dir ? (Lx - 1 - s) : s;

        // stage previous h (whole direction) into SMEM; __ldcg avoids stale L1
        {
            const float4* hs4 = (const float4*)(g_hstate + ((dir << 1) + (s & 1)) * (Hx * Bx));
            float4* hd4 = (float4*)h_sm;
            for (int i = tid; i < (Hx * Bx / 4); i += NTH) hd4[i] = __ldcg(hs4 + i);
        }
        if (IS_L0) {
            const float* xr = x + (size_t)t * Bx * DIN;
            for (int i = tid; i < Bx * DIN; i += NTH) {
                int bb = i / DIN; int kk = i - bb * DIN;
                x_sm[kk * Bx + bb] = xr[i];
            }
        }
        __syncthreads();

        if (valid) {
            float a0 = 0.f, a1 = 0.f, a2 = 0.f, a3 = 0.f;
            #pragma unroll 2
            for (int k = 0; k < Hx; k += 4) {
                const float h0 = h_sm[k * Bx + b];
                const float h1 = h_sm[k * Bx + Bx + b];
                const float h2 = h_sm[k * Bx + 2 * Bx + b];
                const float h3 = h_sm[k * Bx + 3 * Bx + b];
                float4 q;
                q = *(const float4*)(w0 + k); a0 += h0 * q.x + h1 * q.y + h2 * q.z + h3 * q.w;
                q = *(const float4*)(w1 + k); a1 += h0 * q.x + h1 * q.y + h2 * q.z + h3 * q.w;
                q = *(const float4*)(w2 + k); a2 += h0 * q.x + h1 * q.y + h2 * q.z + h3 * q.w;
                q = *(const float4*)(w3 + k); a3 += h0 * q.x + h1 * q.y + h2 * q.z + h3 * q.w;
            }
            if (IS_L0) {
                // fused input projection (K=42, ~5% of recurrent work)
                const float* wi0 = Wih + n * DIN;
                const float* wi1 = wi0 + Hx * DIN;
                const float* wi2 = wi1 + Hx * DIN;
                const float* wi3 = wi2 + Hx * DIN;
                #pragma unroll
                for (int k = 0; k < DIN; k++) {
                    const float xv = x_sm[k * Bx + b];
                    a0 += xv * wi0[k]; a1 += xv * wi1[k];
                    a2 += xv * wi2[k]; a3 += xv * wi3[k];
                }
                a0 += bi0; a1 += bi1; a2 += bi2; a3 += bi3;
            } else {
                const float* gp = G + ((size_t)t * Bx + b) * H4 + n;
                a0 += gp[0]; a1 += gp[Hx]; a2 += gp[2 * Hx]; a3 += gp[3 * Hx];
            }
            const float ig = sigf(a0);
            const float fg = sigf(a1);
            const float gg = tanhf(a2);
            const float og = sigf(a3);
            creg = fg * creg + ig * gg;
            const float h = og * tanhf(creg);
            g_hstate[((dir << 1) + ((s + 1) & 1)) * (Hx * Bx) + n * Bx + b] = h;
            Hout[((size_t)t * Bx + b) * H2x + dir * Hx + n] = h;
        }
        grid_barrier();
    }
}

// ---------------- SGEMM:  C[m][n] = sum_k A[m][k]*B[n][k] + bias1[n]+bias2[n]
// 128x128 tile, BK=16, 8x8 microtile, 256 threads, DOUBLE-BUFFERED smem with
// global->register prefetch. Needs M,N%128==0, K%16==0.
__global__ void __launch_bounds__(256, 2)
sgemm_tt(const float* __restrict__ A, const float* __restrict__ B,
         const float* __restrict__ bias1, const float* __restrict__ bias2,
         float* __restrict__ C, int M, int N, int K)
{
    __shared__ float As[2][16][128];
    __shared__ float Bs[2][16][128];
    const int tid = threadIdx.x;
    const int m0 = blockIdx.y << 7;
    const int n0 = blockIdx.x << 7;
    const int tx = tid & 15, ty = tid >> 4;
    const int lr = tid & 127;
    const int lk = (tid >> 7) << 3;     // 0 or 8

    float acc[8][8];
    #pragma unroll
    for (int i = 0; i < 8; i++)
        #pragma unroll
        for (int j = 0; j < 8; j++) acc[i][j] = 0.f;

    const float* Ap = A + (size_t)(m0 + lr) * K + lk;
    const float* Bp = B + (size_t)(n0 + lr) * K + lk;

    // ---- preload tile 0 into smem[0]
    {
        float4 a0 = *(const float4*)(Ap);
        float4 a1 = *(const float4*)(Ap + 4);
        float4 b0 = *(const float4*)(Bp);
        float4 b1 = *(const float4*)(Bp + 4);
        As[0][lk + 0][lr] = a0.x; As[0][lk + 1][lr] = a0.y; As[0][lk + 2][lr] = a0.z; As[0][lk + 3][lr] = a0.w;
        As[0][lk + 4][lr] = a1.x; As[0][lk + 5][lr] = a1.y; As[0][lk + 6][lr] = a1.z; As[0][lk + 7][lr] = a1.w;
        Bs[0][lk + 0][lr] = b0.x; Bs[0][lk + 1][lr] = b0.y; Bs[0][lk + 2][lr] = b0.z; Bs[0][lk + 3][lr] = b0.w;
        Bs[0][lk + 4][lr] = b1.x; Bs[0][lk + 5][lr] = b1.y; Bs[0][lk + 6][lr] = b1.z; Bs[0][lk + 7][lr] = b1.w;
    }
    __syncthreads();

    const int ktiles = K >> 4;
    int buf = 0;

    for (int kt = 0; kt < ktiles; kt++) {
        // ---- issue global prefetch of next tile EARLY (consumed after compute)
        float4 na0, na1, nb0, nb1;
        const bool has_next = (kt + 1 < ktiles);
        if (has_next) {
            const float* Ap2 = Ap + ((kt + 1) << 4);
            const float* Bp2 = Bp + ((kt + 1) << 4);
            na0 = *(const float4*)(Ap2);
            na1 = *(const float4*)(Ap2 + 4);
            nb0 = *(const float4*)(Bp2);
            nb1 = *(const float4*)(Bp2 + 4);
        }

        // ---- compute on current buffer
        #pragma unroll
        for (int kk = 0; kk < 16; kk++) {
            float ra[8], rb[8];
            *(float4*)&ra[0] = *(const float4*)&As[buf][kk][ty * 8];
            *(float4*)&ra[4] = *(const float4*)&As[buf][kk][ty * 8 + 4];
            *(float4*)&rb[0] = *(const float4*)&Bs[buf][kk][tx * 8];
            *(float4*)&rb[4] = *(const float4*)&Bs[buf][kk][tx * 8 + 4];
            #pragma unroll
            for (int i = 0; i < 8; i++)
                #pragma unroll
                for (int j = 0; j < 8; j++) acc[i][j] += ra[i] * rb[j];
        }

        // ---- store prefetched tile into the other buffer, flip
        if (has_next) {
            const int nb = buf ^ 1;
            As[nb][lk + 0][lr] = na0.x; As[nb][lk + 1][lr] = na0.y; As[nb][lk + 2][lr] = na0.z; As[nb][lk + 3][lr] = na0.w;
            As[nb][lk + 4][lr] = na1.x; As[nb][lk + 5][lr] = na1.y; As[nb][lk + 6][lr] = na1.z; As[nb][lk + 7][lr] = na1.w;
            Bs[nb][lk + 0][lr] = nb0.x; Bs[nb][lk + 1][lr] = nb0.y; Bs[nb][lk + 2][lr] = nb0.z; Bs[nb][lk + 3][lr] = nb0.w;
            Bs[nb][lk + 4][lr] = nb1.x; Bs[nb][lk + 5][lr] = nb1.y; Bs[nb][lk + 6][lr] = nb1.z; Bs[nb][lk + 7][lr] = nb1.w;
            __syncthreads();
            buf = nb;
        }
    }

    float bz[8];
    #pragma unroll
    for (int j = 0; j < 8; j++) {
        int nn = n0 + tx * 8 + j;
        bz[j] = (bias1 ? bias1[nn] : 0.f) + (bias2 ? bias2[nn] : 0.f);
    }
    #pragma unroll
    for (int i = 0; i < 8; i++) {
        float* Crow = C + (size_t)(m0 + ty * 8 + i) * N + n0 + tx * 8;
        float4 o0 = { acc[i][0] + bz[0], acc[i][1] + bz[1], acc[i][2] + bz[2], acc[i][3] + bz[3] };
        float4 o1 = { acc[i][4] + bz[4], acc[i][5] + bz[5], acc[i][6] + bz[6], acc[i][7] + bz[7] };
        *(float4*)(Crow)     = o0;
        *(float4*)(Crow + 4) = o1;
    }
}

// ---------------- head: logits -> softmax -> angle mixture -> atan2 --------
__global__ void __launch_bounds__(128)
head_kernel(const float* __restrict__ H2p, const float* __restrict__ Wlin,
            const float* __restrict__ blin, const float* __restrict__ alpha,
            float* __restrict__ ang)
{
    __shared__ float hs[H2x];
    __shared__ float lg[ASZ];
    const int lb = blockIdx.x;               // t*32 + b
    const int tid = threadIdx.x;
    const int w = tid >> 5, lane = tid & 31;

    const float4* hrow = (const float4*)(H2p + (size_t)lb * H2x);
    for (int i = tid; i < H2x / 4; i += 128) ((float4*)hs)[i] = hrow[i];
    __syncthreads();

    for (int a = w; a < ASZ; a += 4) {
        const float* wr = Wlin + a * H2x;
        float s = 0.f;
        for (int k = lane; k < H2x; k += 32) s += hs[k] * wr[k];
        #pragma unroll
        for (int o = 16; o; o >>= 1) s += __shfl_xor_sync(0xffffffffu, s, o);
        if (lane == 0) lg[a] = s + blin[a];
    }
    __syncthreads();

    if (tid < 32) {
        float v = (lane < ASZ) ? lg[lane] : -1e30f;
        float mx = v;
        #pragma unroll
        for (int o = 16; o; o >>= 1) mx = fmaxf(mx, __shfl_xor_sync(0xffffffffu, mx, o));
        float e = (lane < ASZ) ? expf(v - mx) : 0.f;
        float se = e;
        #pragma unroll
        for (int o = 16; o; o >>= 1) se += __shfl_xor_sync(0xffffffffu, se, o);
        const float p = e / se;
        #pragma unroll
        for (int d = 0; d < 3; d++) {
            float al = (lane < ASZ) ? alpha[lane * 3 + d] : 0.f;
            float ss = p * sinf(al);
            float cc = p * cosf(al);
            #pragma unroll
            for (int o = 16; o; o >>= 1) {
                ss += __shfl_xor_sync(0xffffffffu, ss, o);
                cc += __shfl_xor_sync(0xffffffffu, cc, o);
            }
            if (lane == 0) ang[(size_t)lb * 3 + d] = atan2f(ss, cc);
        }
    }
}

// ---------------- NeRF chain extension (one lane per batch column) ---------
__global__ void __launch_bounds__(32)
nerf_kernel(const float* __restrict__ ang, float* __restrict__ out)
{
    const int b = threadIdx.x;
    const float dl[3]    = { 1.458f, 1.525f, 1.329f };
    const float costh[3] = { (float)cos(3.14159265358979323846 - 2.124),
                             (float)cos(3.14159265358979323846 - 1.941),
                             (float)cos(3.14159265358979323846 - 2.028) };
    const float sinth[3] = { (float)sin(3.14159265358979323846 - 2.124),
                             (float)sin(3.14159265358979323846 - 1.941),
                             (float)sin(3.14159265358979323846 - 2.028) };

    float Ax = 0.f, Ay = 0.f, Az = 0.f;
    float Bxv = 1.458f, Byv = 0.f, Bzv = 0.f;
    float Cx = (float)(1.458 + 1.525 * cos(3.14159265358979323846 - 2.124));
    float Cy = (float)(1.525 * sin(3.14159265358979323846 - 2.124));
    float Cz = 0.f;

    for (int i = 0; i < 3 * Lx; i++) {
        const int l = i / 3, d3 = i - l * 3;
        const float phi = ang[((size_t)l * Bx + b) * 3 + d3];

        float bcx = Cx - Bxv, bcy = Cy - Byv, bcz = Cz - Bzv;
        float nb = sqrtf(bcx * bcx + bcy * bcy + bcz * bcz);
        float inv = 1.f / (nb + 1e-8f);
        bcx *= inv; bcy *= inv; bcz *= inv;

        float abx = Bxv - Ax, aby = Byv - Ay, abz = Bzv - Az;
        float nx = aby * bcz - abz * bcy;
        float ny = abz * bcx - abx * bcz;
        float nz = abx * bcy - aby * bcx;
        float nn = sqrtf(nx * nx + ny * ny + nz * nz);
        float invn = 1.f / (nn + 1e-8f);
        nx *= invn; ny *= invn; nz *= invn;

        float mx = ny * bcz - nz * bcy;
        float my = nz * bcx - nx * bcz;
        float mz = nx * bcy - ny * bcx;

        const float cp = cosf(phi), sp = sinf(phi);
        const float ct = costh[d3], st = sinth[d3], dd = dl[d3];

        float Nx = Cx + dd * (ct * bcx + st * (cp * mx + sp * nx));
        float Ny = Cy + dd * (ct * bcy + st * (cp * my + sp * ny));
        float Nz = Cz + dd * (ct * bcz + st * (cp * mz + sp * nz));

        float* o = out + ((size_t)i * Bx + b) * 3;
        o[0] = Nx; o[1] = Ny; o[2] = Nz;

        Ax = Bxv; Ay = Byv; Az = Bzv;
        Bxv = Cx; Byv = Cy; Bzv = Cz;
        Cx = Nx; Cy = Ny; Cz = Nz;
    }
}

// ---------------- launcher ----------------
extern "C" void kernel_launch(void* const* d_in, const int* in_sizes, int n_in,
                              void* d_out, int out_size)
{
    const float* x     = (const float*)d_in[0];
    const float* Wih0f = (const float*)d_in[1];
    const float* Whh0f = (const float*)d_in[2];
    const float* bih0f = (const float*)d_in[3];
    const float* bhh0f = (const float*)d_in[4];
    const float* Wih0b = (const float*)d_in[5];
    const float* Whh0b = (const float*)d_in[6];
    const float* bih0b = (const float*)d_in[7];
    const float* bhh0b = (const float*)d_in[8];
    const float* Wih1f = (const float*)d_in[9];
    const float* Whh1f = (const float*)d_in[10];
    const float* bih1f = (const float*)d_in[11];
    const float* bhh1f = (const float*)d_in[12];
    const float* Wih1b = (const float*)d_in[13];
    const float* Whh1b = (const float*)d_in[14];
    const float* bih1b = (const float*)d_in[15];
    const float* bhh1b = (const float*)d_in[16];
    const float* W_lin = (const float*)d_in[17];
    const float* b_lin = (const float*)d_in[18];
    const float* alpha = (const float*)d_in[19];
    float* out = (float*)d_out;

    float *pH1, *pH2, *pGf, *pGb, *pAng;
    cudaGetSymbolAddress((void**)&pH1,  g_H1);
    cudaGetSymbolAddress((void**)&pH2,  g_H2);
    cudaGetSymbolAddress((void**)&pGf,  g_G1f);
    cudaGetSymbolAddress((void**)&pGb,  g_G1b);
    cudaGetSymbolAddress((void**)&pAng, g_ang);

    const int smem = (Hx * Bx + Bx * DIN) * (int)sizeof(float);
    cudaFuncSetAttribute(lstm_kernel<true>,  cudaFuncAttributeMaxDynamicSharedMemorySize, smem);
    cudaFuncSetAttribute(lstm_kernel<false>, cudaFuncAttributeMaxDynamicSharedMemorySize, smem);

    // Layer 0 (input projection fused; K=42)
    lstm_kernel<true><<<NBLK, NTH, smem>>>(x, Wih0f, Wih0b, bih0f, bhh0f, bih0b, bhh0b,
                                           nullptr, nullptr, Whh0f, Whh0b, pH1);

    // Layer-1 input gates: two big GEMMs with fused biases
    dim3 gg(H4 / 128, (Lx * Bx) / 128);
    sgemm_tt<<<gg, 256>>>(pH1, Wih1f, bih1f, bhh1f, pGf, Lx * Bx, H4, H2x);
    sgemm_tt<<<gg, 256>>>(pH1, Wih1b, bih1b, bhh1b, pGb, Lx * Bx, H4, H2x);

    // Layer 1 (gates precomputed)
    lstm_kernel<false><<<NBLK, NTH, smem>>>(nullptr, nullptr, nullptr,
                                            nullptr, nullptr, nullptr, nullptr,
                                            pGf, pGb, Whh1f, Whh1b, pH2);

    head_kernel<<<Lx * Bx, 128>>>(pH2, W_lin, b_lin, alpha, pAng);
    nerf_kernel<<<1, 32>>>(pAng, out);
}